// round 1
// baseline (speedup 1.0000x reference)
#include <cuda_runtime.h>
#include <cuda_bf16.h>
#include <cstdint>

#define NLAYERS 4
#define HID 512
#define BATCH 32
#define SEQ 2048
#define MTOT (BATCH*SEQ)          // 65536

// ---------------- GEMM tiling ----------------
#define BM 128
#define BN 128
#define BK 32
#define LDA 40                    // BK + 8 pad  (row = 80B, 16B-aligned, conflict-free ldmatrix)
#define LDB 136                   // BN + 8 pad  (row = 272B, 16B-aligned, conflict-free ldmatrix)
#define SMEM_BYTES ((2*2*BM*LDA + 2*2*BK*LDB) * 2)   // 75776 bytes

// ---------------- scratch (no cudaMalloc allowed) ----------------
__device__ float g_k[(size_t)MTOT * HID];   // pre-activation of z-gate GEMM
__device__ float g_p[(size_t)MTOT * HID];   // pre-activation of h~ GEMM
__device__ float g_h[(size_t)MTOT * HID];   // scan output

// ---------------- helpers ----------------
__device__ __forceinline__ uint32_t saddr(const void* p) {
    return (uint32_t)__cvta_generic_to_shared(p);
}

__device__ __forceinline__ void ldm_x4(uint32_t* r, uint32_t a) {
    asm volatile("ldmatrix.sync.aligned.m8n8.x4.shared.b16 {%0,%1,%2,%3}, [%4];"
                 : "=r"(r[0]), "=r"(r[1]), "=r"(r[2]), "=r"(r[3]) : "r"(a));
}
__device__ __forceinline__ void ldm_x2t(uint32_t* r, uint32_t a) {
    asm volatile("ldmatrix.sync.aligned.m8n8.x2.trans.shared.b16 {%0,%1}, [%2];"
                 : "=r"(r[0]), "=r"(r[1]) : "r"(a));
}
__device__ __forceinline__ void mma16816(float* c, const uint32_t* a, const uint32_t* b) {
    asm volatile(
        "mma.sync.aligned.m16n8k16.row.col.f32.bf16.bf16.f32 "
        "{%0,%1,%2,%3}, {%4,%5,%6,%7}, {%8,%9}, {%0,%1,%2,%3};"
        : "+f"(c[0]), "+f"(c[1]), "+f"(c[2]), "+f"(c[3])
        : "r"(a[0]), "r"(a[1]), "r"(a[2]), "r"(a[3]), "r"(b[0]), "r"(b[1]));
}

// split x into bf16 hi + bf16 lo (x ~= hi + lo), store pair-packed
__device__ __forceinline__ void split2(float x, float y,
                                       __nv_bfloat16* hp, __nv_bfloat16* lp) {
    __nv_bfloat16 hx = __float2bfloat16(x);
    __nv_bfloat16 hy = __float2bfloat16(y);
    __nv_bfloat16 lx = __float2bfloat16(x - __bfloat162float(hx));
    __nv_bfloat16 ly = __float2bfloat16(y - __bfloat162float(hy));
    *reinterpret_cast<__nv_bfloat162*>(hp) = __halves2bfloat162(hx, hy);
    *reinterpret_cast<__nv_bfloat162*>(lp) = __halves2bfloat162(lx, ly);
}

// ============================================================================
// Fused dual GEMM: k = cur@Wz + bz  and  p = cur@Wh + bh.
// bf16x3 split precision (error ~2^-17 on inputs), fp32 accumulation.
// grid = (8, MTOT/128): blockIdx.x = {4 n-tiles} x {z / h}; consecutive
// blocks share the same A m-tile -> A streamed from DRAM once (L2 reuse).
// ============================================================================
__global__ void __launch_bounds__(256, 1) gates_gemm(
    const float* __restrict__ A, const float* __restrict__ Wz,
    const float* __restrict__ Wh, const float* __restrict__ bz,
    const float* __restrict__ bh)
{
    extern __shared__ __align__(16) char smem_raw[];
    __nv_bfloat16* s = (__nv_bfloat16*)smem_raw;

    const int tid  = threadIdx.x;
    const int lane = tid & 31;
    const int warp = tid >> 5;
    const int wm   = warp >> 2;            // 0..1  (64-row warp tile)
    const int wn   = warp & 3;             // 0..3  (32-col warp tile)
    const int zsel = blockIdx.x >> 2;      // 0 -> Wz/bz/g_k, 1 -> Wh/bh/g_p
    const int colBase = (blockIdx.x & 3) * BN;
    const size_t rowBase = (size_t)blockIdx.y * BM;

    const float* W    = zsel ? Wh : Wz;
    const float* bias = zsel ? bh : bz;
    float*       Out  = zsel ? g_p : g_k;

    const int am = tid >> 1, af = tid & 1;   // A loader: row, float4-phase
    const int bk = tid >> 3, bf_ = tid & 7;  // B loader: row, float4-phase

    float4 ra[4], rb[4];

    auto load_g = [&](int kt) {
        const float4* Ap = (const float4*)(A + (rowBase + am) * HID + kt * BK);
        const float4* Bp = (const float4*)(W + (size_t)(kt * BK + bk) * HID + colBase);
#pragma unroll
        for (int j = 0; j < 4; ++j) {
            ra[j] = Ap[af + 2 * j];
            rb[j] = Bp[bf_ + 8 * j];
        }
    };
    auto store_s = [&](int st) {
        __nv_bfloat16* sAh = s + st * (2 * BM * LDA);
        __nv_bfloat16* sAl = sAh + BM * LDA;
        __nv_bfloat16* sBh = s + 2 * (2 * BM * LDA) + st * (2 * BK * LDB);
        __nv_bfloat16* sBl = sBh + BK * LDB;
#pragma unroll
        for (int j = 0; j < 4; ++j) {
            int k0 = (af + 2 * j) * 4;
            split2(ra[j].x, ra[j].y, sAh + am * LDA + k0,     sAl + am * LDA + k0);
            split2(ra[j].z, ra[j].w, sAh + am * LDA + k0 + 2, sAl + am * LDA + k0 + 2);
            int n0 = (bf_ + 8 * j) * 4;
            split2(rb[j].x, rb[j].y, sBh + bk * LDB + n0,     sBl + bk * LDB + n0);
            split2(rb[j].z, rb[j].w, sBh + bk * LDB + n0 + 2, sBl + bk * LDB + n0 + 2);
        }
    };

    float acc[4][4][4];
#pragma unroll
    for (int mt = 0; mt < 4; ++mt)
#pragma unroll
        for (int nt = 0; nt < 4; ++nt)
#pragma unroll
            for (int r = 0; r < 4; ++r) acc[mt][nt][r] = 0.f;

    auto comp = [&](int st) {
        const __nv_bfloat16* sAh = s + st * (2 * BM * LDA);
        const __nv_bfloat16* sAl = sAh + BM * LDA;
        const __nv_bfloat16* sBh = s + 2 * (2 * BM * LDA) + st * (2 * BK * LDB);
        const __nv_bfloat16* sBl = sBh + BK * LDB;
#pragma unroll
        for (int ks = 0; ks < 2; ++ks) {
            uint32_t Ah[4][4], Al[4][4], Bh[4][2], Bl[4][2];
#pragma unroll
            for (int mt = 0; mt < 4; ++mt) {
                int ar = wm * 64 + mt * 16 + (lane & 15);
                int ac = ks * 16 + ((lane >> 4) << 3);
                ldm_x4(Ah[mt], saddr(sAh + ar * LDA + ac));
                ldm_x4(Al[mt], saddr(sAl + ar * LDA + ac));
            }
#pragma unroll
            for (int nt = 0; nt < 4; ++nt) {
                int br = ks * 16 + (lane & 15);
                int bc = wn * 32 + nt * 8;
                ldm_x2t(Bh[nt], saddr(sBh + br * LDB + bc));
                ldm_x2t(Bl[nt], saddr(sBl + br * LDB + bc));
            }
#pragma unroll
            for (int mt = 0; mt < 4; ++mt)
#pragma unroll
                for (int nt = 0; nt < 4; ++nt) {
                    mma16816(acc[mt][nt], Ah[mt], Bh[nt]);   // hi*hi
                    mma16816(acc[mt][nt], Ah[mt], Bl[nt]);   // hi*lo
                    mma16816(acc[mt][nt], Al[mt], Bh[nt]);   // lo*hi
                }
        }
    };

    load_g(0);
    store_s(0);
    __syncthreads();
    const int KI = HID / BK;   // 16
    for (int kt = 0; kt < KI; ++kt) {
        int st = kt & 1;
        if (kt + 1 < KI) load_g(kt + 1);
        comp(st);
        if (kt + 1 < KI) { store_s(st ^ 1); __syncthreads(); }
    }

    // epilogue: add bias, store fp32
#pragma unroll
    for (int mt = 0; mt < 4; ++mt) {
        size_t r0 = rowBase + wm * 64 + mt * 16 + (lane >> 2);
#pragma unroll
        for (int nt = 0; nt < 4; ++nt) {
            int cb = colBase + wn * 32 + nt * 8 + ((lane & 3) << 1);
            float2 bs = *(const float2*)(bias + cb);
            float2 o0 = make_float2(acc[mt][nt][0] + bs.x, acc[mt][nt][1] + bs.y);
            float2 o1 = make_float2(acc[mt][nt][2] + bs.x, acc[mt][nt][3] + bs.y);
            *(float2*)(Out + r0 * HID + cb)       = o0;
            *(float2*)(Out + (r0 + 8) * HID + cb) = o1;
        }
    }
}

// ============================================================================
// Sequential scan:  h_t = sigmoid(-k_t)*h_{t-1} + sigmoid(k_t)*g(p_t)
// (exactly equal to the reference's log-space formulation; all terms > 0)
// One thread per (b, channel) chain; 64-thread blocks to spread across SMs.
// Also emits hiddens[i] = h_{T-1}.
// ============================================================================
__global__ void __launch_bounds__(64) scan_kernel(const float* __restrict__ h0l,
                                                  float* __restrict__ hid_out)
{
    int b = blockIdx.x >> 3;
    int c = ((blockIdx.x & 7) << 6) + threadIdx.x;
    size_t base = ((size_t)b * SEQ) * HID + c;
    const float* kp = g_k + base;
    const float* pp = g_p + base;
    float*       hp = g_h + base;

    float x0 = h0l[b * HID + c];
    float hprev = (x0 >= 0.f) ? (x0 + 0.5f)
                              : __fdividef(1.f, 1.f + __expf(-x0));
#pragma unroll 8
    for (int t = 0; t < SEQ; ++t) {
        float kv = __ldcs(kp + (size_t)t * HID);
        float pv = __ldcs(pp + (size_t)t * HID);
        float ek = __expf(-kv);
        float z  = __fdividef(1.f, 1.f + ek);   // sigmoid(k)
        float a  = ek * z;                       // sigmoid(-k) = 1 - z
        float gp = (pv >= 0.f) ? (pv + 0.5f)
                               : __fdividef(1.f, 1.f + __expf(-pv));
        float h = fmaf(a, hprev, z * gp);
        __stcs(hp + (size_t)t * HID, h);
        hprev = h;
    }
    hid_out[b * HID + c] = hprev;
}

// ============================================================================
// LayerNorm(h) * gamma + beta + residual  -> cur   (one warp per row)
// ============================================================================
__global__ void __launch_bounds__(256) ln_resid(const float* __restrict__ resid,
                                                const float* __restrict__ gamma,
                                                const float* __restrict__ beta,
                                                float* __restrict__ outp)
{
    int warp = threadIdx.x >> 5, lane = threadIdx.x & 31;
    size_t row = (size_t)blockIdx.x * 8 + warp;
    const float4* hr = (const float4*)(g_h + row * HID);

    float4 hv[4];
    float s = 0.f, s2 = 0.f;
#pragma unroll
    for (int j = 0; j < 4; ++j) {
        hv[j] = __ldcs(hr + lane + 32 * j);
        s  += hv[j].x + hv[j].y + hv[j].z + hv[j].w;
        s2 += hv[j].x * hv[j].x + hv[j].y * hv[j].y +
              hv[j].z * hv[j].z + hv[j].w * hv[j].w;
    }
#pragma unroll
    for (int o = 16; o; o >>= 1) {
        s  += __shfl_xor_sync(0xffffffffu, s,  o);
        s2 += __shfl_xor_sync(0xffffffffu, s2, o);
    }
    float mu   = s * (1.f / HID);
    float var  = fmaf(s2, 1.f / HID, -mu * mu);
    float rstd = rsqrtf(var + 1e-5f);

    const float4* rr  = (const float4*)(resid + row * HID);
    float4*       op  = (float4*)(outp + row * HID);
    const float4* g4p = (const float4*)gamma;
    const float4* b4p = (const float4*)beta;
#pragma unroll
    for (int j = 0; j < 4; ++j) {
        int c4 = lane + 32 * j;
        float4 g4 = __ldg(g4p + c4);
        float4 b4 = __ldg(b4p + c4);
        float4 r4 = rr[c4];
        float4 o;
        o.x = (hv[j].x - mu) * rstd * g4.x + b4.x + r4.x;
        o.y = (hv[j].y - mu) * rstd * g4.y + b4.y + r4.y;
        o.z = (hv[j].z - mu) * rstd * g4.z + b4.z + r4.z;
        o.w = (hv[j].w - mu) * rstd * g4.w + b4.w + r4.w;
        op[c4] = o;
    }
}

// ============================================================================
extern "C" void kernel_launch(void* const* d_in, const int* in_sizes, int n_in,
                              void* d_out, int out_size)
{
    const float* x     = (const float*)d_in[0];
    const float* h0    = (const float*)d_in[1];
    const float* Wz    = (const float*)d_in[2];
    const float* bz    = (const float*)d_in[3];
    const float* Wh    = (const float*)d_in[4];
    const float* bh    = (const float*)d_in[5];
    const float* gamma = (const float*)d_in[6];
    const float* beta  = (const float*)d_in[7];

    float* out_cur = (float*)d_out;                       // (B, T, H)
    float* out_hid = out_cur + (size_t)MTOT * HID;        // (L, B, H)

    cudaFuncSetAttribute(gates_gemm,
                         cudaFuncAttributeMaxDynamicSharedMemorySize, SMEM_BYTES);

    const float* cur = x;
    for (int i = 0; i < NLAYERS; ++i) {
        gates_gemm<<<dim3(8, MTOT / BM), 256, SMEM_BYTES>>>(
            cur, Wz + (size_t)i * HID * HID, Wh + (size_t)i * HID * HID,
            bz + i * HID, bh + i * HID);
        scan_kernel<<<BATCH * 8, 64>>>(h0 + (size_t)i * BATCH * HID,
                                       out_hid + (size_t)i * BATCH * HID);
        ln_resid<<<MTOT / 8, 256>>>(cur, gamma + i * HID, beta + i * HID, out_cur);
        cur = out_cur;
    }
}

// round 2
// speedup vs baseline: 2.6927x; 2.6927x over previous
#include <cuda_runtime.h>
#include <cuda_bf16.h>
#include <cstdint>

#define NLAYERS 4
#define HID 512
#define BATCH 32
#define SEQ 2048
#define MTOT (BATCH*SEQ)          // 65536
#define NC 16                     // scan chunks
#define TC (SEQ/NC)               // 128 steps per chunk

// ---------------- GEMM tiling ----------------
#define BM 128
#define BN 128
#define BK 32
#define LDA 40                    // BK + 8 pad (row = 80B)
#define LDB 136                   // BN + 8 pad (row = 272B)
#define STAGE_EL (2*BM*LDA + 2*BK*LDB)            // 18944 bf16
#define SMEM_BYTES (2*STAGE_EL*2)                 // 75776 bytes

// ---------------- scratch ----------------
__device__ float g_k[(size_t)MTOT * HID];
__device__ float g_p[(size_t)MTOT * HID];
__device__ float g_S[(size_t)MTOT * HID];         // chunk-local partial h
__device__ float g_P[(size_t)MTOT * HID];         // chunk-local prefix prod
__device__ __nv_bfloat16 g_Ah[(size_t)MTOT * HID];
__device__ __nv_bfloat16 g_Al[(size_t)MTOT * HID];
__device__ __nv_bfloat16 g_Wsp_hi[(size_t)NLAYERS * 2 * HID * HID];
__device__ __nv_bfloat16 g_Wsp_lo[(size_t)NLAYERS * 2 * HID * HID];
__device__ float g_cA[BATCH * NC * HID];
__device__ float g_cB[BATCH * NC * HID];
__device__ float g_hin[BATCH * NC * HID];

// ---------------- helpers ----------------
__device__ __forceinline__ uint32_t saddr(const void* p) {
    return (uint32_t)__cvta_generic_to_shared(p);
}
__device__ __forceinline__ void cpasync16(void* smem, const void* g) {
    asm volatile("cp.async.cg.shared.global [%0], [%1], 16;"
                 :: "r"(saddr(smem)), "l"(g));
}
__device__ __forceinline__ void cp_commit() {
    asm volatile("cp.async.commit_group;");
}
__device__ __forceinline__ void cp_wait0() {
    asm volatile("cp.async.wait_group 0;");
}
__device__ __forceinline__ void ldm_x4(uint32_t* r, uint32_t a) {
    asm volatile("ldmatrix.sync.aligned.m8n8.x4.shared.b16 {%0,%1,%2,%3}, [%4];"
                 : "=r"(r[0]), "=r"(r[1]), "=r"(r[2]), "=r"(r[3]) : "r"(a));
}
__device__ __forceinline__ void ldm_x2t(uint32_t* r, uint32_t a) {
    asm volatile("ldmatrix.sync.aligned.m8n8.x2.trans.shared.b16 {%0,%1}, [%2];"
                 : "=r"(r[0]), "=r"(r[1]) : "r"(a));
}
__device__ __forceinline__ void mma16816(float* c, const uint32_t* a, const uint32_t* b) {
    asm volatile(
        "mma.sync.aligned.m16n8k16.row.col.f32.bf16.bf16.f32 "
        "{%0,%1,%2,%3}, {%4,%5,%6,%7}, {%8,%9}, {%0,%1,%2,%3};"
        : "+f"(c[0]), "+f"(c[1]), "+f"(c[2]), "+f"(c[3])
        : "r"(a[0]), "r"(a[1]), "r"(a[2]), "r"(a[3]), "r"(b[0]), "r"(b[1]));
}
__device__ __forceinline__ void split2(float x, float y,
                                       __nv_bfloat16* hp, __nv_bfloat16* lp) {
    __nv_bfloat16 hx = __float2bfloat16(x);
    __nv_bfloat16 hy = __float2bfloat16(y);
    __nv_bfloat16 lx = __float2bfloat16(x - __bfloat162float(hx));
    __nv_bfloat16 ly = __float2bfloat16(y - __bfloat162float(hy));
    *reinterpret_cast<__nv_bfloat162*>(hp) = __halves2bfloat162(hx, hy);
    *reinterpret_cast<__nv_bfloat162*>(lp) = __halves2bfloat162(lx, ly);
}

// ============================================================================
// One-shot conversion kernels
// ============================================================================
__global__ void __launch_bounds__(256) split_w(const float* __restrict__ Wz,
                                               const float* __restrict__ Wh) {
    size_t i = (size_t)blockIdx.x * 256 + threadIdx.x;    // over 4*512*512
    size_t l = i >> 18, r = i & ((1u << 18) - 1);
    float z = Wz[i], h = Wh[i];
    {
        size_t o = ((l * 2 + 0) << 18) + r;
        __nv_bfloat16 hi = __float2bfloat16(z);
        g_Wsp_hi[o] = hi;
        g_Wsp_lo[o] = __float2bfloat16(z - __bfloat162float(hi));
    }
    {
        size_t o = ((l * 2 + 1) << 18) + r;
        __nv_bfloat16 hi = __float2bfloat16(h);
        g_Wsp_hi[o] = hi;
        g_Wsp_lo[o] = __float2bfloat16(h - __bfloat162float(hi));
    }
}

__global__ void __launch_bounds__(256) split_x(const float* __restrict__ x) {
    size_t i = (size_t)blockIdx.x * 256 + threadIdx.x;    // over MTOT*HID/2
    float2 v = ((const float2*)x)[i];
    split2(v.x, v.y, g_Ah + 2 * i, g_Al + 2 * i);
}

// ============================================================================
// Fused dual GEMM (bf16x3): reads pre-split bf16 A and W via cp.async.
// grid = (8, MTOT/128): blockIdx.x = {4 n-tiles} x {z / h}.
// ============================================================================
__global__ void __launch_bounds__(256, 2) gates_gemm(
    int layer, const float* __restrict__ bz, const float* __restrict__ bh)
{
    extern __shared__ __align__(16) char smem_raw[];
    __nv_bfloat16* s = (__nv_bfloat16*)smem_raw;

    const int tid  = threadIdx.x;
    const int lane = tid & 31;
    const int warp = tid >> 5;
    const int wm   = warp >> 2;
    const int wn   = warp & 3;
    const int zsel = blockIdx.x >> 2;
    const int colBase = (blockIdx.x & 3) * BN;
    const size_t rowBase = (size_t)blockIdx.y * BM;

    const __nv_bfloat16* Wh_ = g_Wsp_hi + (((size_t)layer * 2 + zsel) << 18);
    const __nv_bfloat16* Wl_ = g_Wsp_lo + (((size_t)layer * 2 + zsel) << 18);
    const float* bias = zsel ? bh : bz;
    float*       Out  = zsel ? g_p : g_k;

    auto issue = [&](int kt, int st) {
        __nv_bfloat16* sb = s + st * STAGE_EL;
#pragma unroll
        for (int j = 0; j < 4; ++j) {                  // A: 1024 16B chunks
            int i = tid + 256 * j;
            int row = i >> 3, rem = i & 7, hl = rem >> 2, ch = rem & 3;
            const __nv_bfloat16* gsrc = (hl ? g_Al : g_Ah)
                + (rowBase + row) * HID + kt * BK + ch * 8;
            cpasync16(sb + hl * (BM * LDA) + row * LDA + ch * 8, gsrc);
        }
#pragma unroll
        for (int j = 0; j < 4; ++j) {                  // B: 1024 16B chunks
            int i = tid + 256 * j;
            int row = i >> 5, rem = i & 31, hl = rem >> 4, ch = rem & 15;
            const __nv_bfloat16* gsrc = (hl ? Wl_ : Wh_)
                + (size_t)(kt * BK + row) * HID + colBase + ch * 8;
            cpasync16(sb + 2 * BM * LDA + hl * (BK * LDB) + row * LDB + ch * 8, gsrc);
        }
        cp_commit();
    };

    float acc[4][4][4];
#pragma unroll
    for (int mt = 0; mt < 4; ++mt)
#pragma unroll
        for (int nt = 0; nt < 4; ++nt)
#pragma unroll
            for (int r = 0; r < 4; ++r) acc[mt][nt][r] = 0.f;

    auto comp = [&](int st) {
        const __nv_bfloat16* sAh = s + st * STAGE_EL;
        const __nv_bfloat16* sAl = sAh + BM * LDA;
        const __nv_bfloat16* sBh = sAh + 2 * BM * LDA;
        const __nv_bfloat16* sBl = sBh + BK * LDB;
#pragma unroll
        for (int ks = 0; ks < 2; ++ks) {
            uint32_t Bh[4][2], Bl[4][2];
#pragma unroll
            for (int nt = 0; nt < 4; ++nt) {
                int br = ks * 16 + (lane & 15);
                int bc = wn * 32 + nt * 8;
                ldm_x2t(Bh[nt], saddr(sBh + br * LDB + bc));
                ldm_x2t(Bl[nt], saddr(sBl + br * LDB + bc));
            }
#pragma unroll
            for (int mt = 0; mt < 4; ++mt) {
                uint32_t Ah[4], Al[4];
                int ar = wm * 64 + mt * 16 + (lane & 15);
                int ac = ks * 16 + ((lane >> 4) << 3);
                ldm_x4(Ah, saddr(sAh + ar * LDA + ac));
                ldm_x4(Al, saddr(sAl + ar * LDA + ac));
#pragma unroll
                for (int nt = 0; nt < 4; ++nt) {
                    mma16816(acc[mt][nt], Ah, Bh[nt]);
                    mma16816(acc[mt][nt], Ah, Bl[nt]);
                    mma16816(acc[mt][nt], Al, Bh[nt]);
                }
            }
        }
    };

    issue(0, 0);
    const int KI = HID / BK;    // 16
    for (int kt = 0; kt < KI; ++kt) {
        int st = kt & 1;
        cp_wait0();
        __syncthreads();
        if (kt + 1 < KI) issue(kt + 1, st ^ 1);
        comp(st);
    }

#pragma unroll
    for (int mt = 0; mt < 4; ++mt) {
        size_t r0 = rowBase + wm * 64 + mt * 16 + (lane >> 2);
#pragma unroll
        for (int nt = 0; nt < 4; ++nt) {
            int cb = colBase + wn * 32 + nt * 8 + ((lane & 3) << 1);
            float2 bs = *(const float2*)(bias + cb);
            float2 o0 = make_float2(acc[mt][nt][0] + bs.x, acc[mt][nt][1] + bs.y);
            float2 o1 = make_float2(acc[mt][nt][2] + bs.x, acc[mt][nt][3] + bs.y);
            *(float2*)(Out + r0 * HID + cb)       = o0;
            *(float2*)(Out + (r0 + 8) * HID + cb) = o1;
        }
    }
}

// ============================================================================
// Scan phase A: per-chunk partials.  h_t = S_t + P_t * h_chunk_in
//   a_t = sigmoid(-k_t), b_t = sigmoid(k_t)*g(p_t)
//   S_t = a_t S_{t-1} + b_t (S_{-1}=0),  P_t = a_t P_{t-1} (P_{-1}=1)
// grid = BATCH*NC*4 blocks x 128 threads (262144 independent chains of 128).
// ============================================================================
__global__ void __launch_bounds__(128) scanA() {
    int b     = blockIdx.x >> 6;
    int chunk = (blockIdx.x >> 2) & 15;
    int c     = (blockIdx.x & 3) * 128 + threadIdx.x;
    size_t base = ((size_t)b * SEQ + chunk * TC) * HID + c;

    float S = 0.f, P = 1.f;
#pragma unroll 4
    for (int t = 0; t < TC; ++t) {
        size_t o = base + (size_t)t * HID;
        float kv = __ldcs(g_k + o);
        float pv = __ldcs(g_p + o);
        float ek = __expf(-kv);
        float z  = __fdividef(1.f, 1.f + ek);
        float a  = ek * z;
        float gp = (pv >= 0.f) ? (pv + 0.5f)
                               : __fdividef(1.f, 1.f + __expf(-pv));
        S = fmaf(a, S, z * gp);
        P *= a;
        __stcs(g_S + o, S);
        __stcs(g_P + o, P);
    }
    g_cA[(b * NC + chunk) * HID + c] = P;
    g_cB[(b * NC + chunk) * HID + c] = S;
}

// ============================================================================
// Scan phase B: chain the NC chunk summaries; emit per-chunk h_in and hiddens.
// ============================================================================
__global__ void __launch_bounds__(256) scanB(const float* __restrict__ h0l,
                                             float* __restrict__ hid_out) {
    int idx = blockIdx.x * 256 + threadIdx.x;   // 16384
    int b = idx >> 9, c = idx & 511;
    float x0 = h0l[b * HID + c];
    float h = (x0 >= 0.f) ? (x0 + 0.5f)
                          : __fdividef(1.f, 1.f + __expf(-x0));
#pragma unroll
    for (int j = 0; j < NC; ++j) {
        g_hin[(b * NC + j) * HID + c] = h;
        h = fmaf(g_cA[(b * NC + j) * HID + c], h, g_cB[(b * NC + j) * HID + c]);
    }
    hid_out[b * HID + c] = h;
}

// ============================================================================
// Phase C: h = S + P*h_in, LayerNorm + residual -> out; optionally write the
// bf16 hi/lo split of out for the next layer's GEMM.
// One block per (b,t) row, 128 threads, 4 channels each.
// ============================================================================
__global__ void __launch_bounds__(128) phaseC(const float* __restrict__ resid,
                                              const float* __restrict__ gamma,
                                              const float* __restrict__ beta,
                                              float* __restrict__ outp,
                                              int write_split) {
    size_t row = blockIdx.x;
    int b = (int)(row >> 11);
    int t = (int)(row & 2047);
    int chunk = t >> 7;
    int tid = threadIdx.x, lane = tid & 31, warp = tid >> 5;

    float4 S4 = __ldcs((const float4*)(g_S + row * HID) + tid);
    float4 P4 = __ldcs((const float4*)(g_P + row * HID) + tid);
    float4 hin4 = *((const float4*)(g_hin + (size_t)(b * NC + chunk) * HID) + tid);

    float4 h;
    h.x = fmaf(P4.x, hin4.x, S4.x);
    h.y = fmaf(P4.y, hin4.y, S4.y);
    h.z = fmaf(P4.z, hin4.z, S4.z);
    h.w = fmaf(P4.w, hin4.w, S4.w);

    float s  = h.x + h.y + h.z + h.w;
    float s2 = h.x * h.x + h.y * h.y + h.z * h.z + h.w * h.w;
#pragma unroll
    for (int o = 16; o; o >>= 1) {
        s  += __shfl_xor_sync(0xffffffffu, s,  o);
        s2 += __shfl_xor_sync(0xffffffffu, s2, o);
    }
    __shared__ float buf[8];
    if (lane == 0) { buf[2 * warp] = s; buf[2 * warp + 1] = s2; }
    __syncthreads();
    s  = buf[0] + buf[2] + buf[4] + buf[6];
    s2 = buf[1] + buf[3] + buf[5] + buf[7];

    float mu   = s * (1.f / HID);
    float var  = fmaf(s2, 1.f / HID, -mu * mu);
    float rstd = rsqrtf(var + 1e-5f);

    float4 g4 = __ldg((const float4*)gamma + tid);
    float4 b4 = __ldg((const float4*)beta + tid);
    float4 r4 = *((const float4*)(resid + row * HID) + tid);
    float4 o;
    o.x = (h.x - mu) * rstd * g4.x + b4.x + r4.x;
    o.y = (h.y - mu) * rstd * g4.y + b4.y + r4.y;
    o.z = (h.z - mu) * rstd * g4.z + b4.z + r4.z;
    o.w = (h.w - mu) * rstd * g4.w + b4.w + r4.w;
    *((float4*)(outp + row * HID) + tid) = o;

    if (write_split) {
        __nv_bfloat16* ah = g_Ah + row * HID + 4 * tid;
        __nv_bfloat16* al = g_Al + row * HID + 4 * tid;
        split2(o.x, o.y, ah, al);
        split2(o.z, o.w, ah + 2, al + 2);
    }
}

// ============================================================================
extern "C" void kernel_launch(void* const* d_in, const int* in_sizes, int n_in,
                              void* d_out, int out_size)
{
    const float* x     = (const float*)d_in[0];
    const float* h0    = (const float*)d_in[1];
    const float* Wz    = (const float*)d_in[2];
    const float* bz    = (const float*)d_in[3];
    const float* Wh    = (const float*)d_in[4];
    const float* bh    = (const float*)d_in[5];
    const float* gamma = (const float*)d_in[6];
    const float* beta  = (const float*)d_in[7];

    float* out_cur = (float*)d_out;                       // (B, T, H)
    float* out_hid = out_cur + (size_t)MTOT * HID;        // (L, B, H)

    cudaFuncSetAttribute(gates_gemm,
                         cudaFuncAttributeMaxDynamicSharedMemorySize, SMEM_BYTES);

    split_w<<<(NLAYERS * HID * HID) / 256, 256>>>(Wz, Wh);
    split_x<<<(MTOT * HID / 2) / 256, 256>>>(x);

    const float* cur = x;
    for (int i = 0; i < NLAYERS; ++i) {
        gates_gemm<<<dim3(8, MTOT / BM), 256, SMEM_BYTES>>>(
            i, bz + i * HID, bh + i * HID);
        scanA<<<BATCH * NC * 4, 128>>>();
        scanB<<<64, 256>>>(h0 + (size_t)i * BATCH * HID,
                           out_hid + (size_t)i * BATCH * HID);
        phaseC<<<MTOT, 128>>>(cur, gamma + i * HID, beta + i * HID,
                              out_cur, (i < NLAYERS - 1) ? 1 : 0);
        cur = out_cur;
    }
}